// round 2
// baseline (speedup 1.0000x reference)
#include <cuda_runtime.h>
#include <math.h>

#define NITEMS   32768
#define DIM      512
#define KSEL     16
#define LAMBDA   0.5f
#define DECAYF   0.85f
#define NTHREADS 1024
#define MAXB     512

// ---------------- device globals (scratch; no allocations allowed) ----------------
__device__ float               g_pmax_part[MAXB];
__device__ float               g_psum_part[MAXB];
__device__ unsigned long long  g_best[2][MAXB];     // double-buffered per-block argmax partials
__device__ float               g_rel[NITEMS];       // softmax(predictions)
__device__ float               g_inv[NITEMS];       // 1/(||E_i||+1e-12)
__device__ float               g_maxsim[NITEMS];    // running max cos-sim to selected set (1e30 = masked)
__device__ float               g_err[KSEL];
__device__ int                 g_sel[KSEL];
__device__ unsigned int        g_bar;               // monotonic grid-barrier counter

// ---------------- monotonic grid barrier (grid is co-resident by construction) ----
__device__ __forceinline__ void grid_sync(int nb) {
    __syncthreads();
    if (threadIdx.x == 0) {
        __threadfence();
        unsigned int ticket = atomicAdd(&g_bar, 1u) + 1u;
        unsigned int target = ((ticket + (unsigned)nb - 1u) / (unsigned)nb) * (unsigned)nb;
        while (*((volatile unsigned int*)&g_bar) < target) { /* spin */ }
        __threadfence();
    }
    __syncthreads();
}

// order-preserving float->u32 map; low 32 bits = ~row so ties pick the SMALLEST row
__device__ __forceinline__ unsigned long long pack_si(float s, int row) {
    unsigned int b = __float_as_uint(s);
    unsigned int e = (b & 0x80000000u) ? ~b : (b | 0x80000000u);
    return ((unsigned long long)e << 32) | (unsigned int)(~row);
}

__device__ __forceinline__ float warp_sum(float v) {
    #pragma unroll
    for (int o = 16; o > 0; o >>= 1) v += __shfl_down_sync(0xffffffffu, v, o);
    return v;
}
__device__ __forceinline__ float warp_max(float v) {
    #pragma unroll
    for (int o = 16; o > 0; o >>= 1) v = fmaxf(v, __shfl_down_sync(0xffffffffu, v, o));
    return v;
}
__device__ __forceinline__ unsigned long long warp_max_u64(unsigned long long v) {
    #pragma unroll
    for (int o = 16; o > 0; o >>= 1) {
        unsigned long long u = __shfl_down_sync(0xffffffffu, v, o);
        if (u > v) v = u;
    }
    return v;
}

// block reduces (valid at thread 0); callers must have all threads participate
__device__ __forceinline__ float blk_max_f(float v, float* sh) {
    v = warp_max(v);
    __syncthreads();
    if ((threadIdx.x & 31) == 0) sh[threadIdx.x >> 5] = v;
    __syncthreads();
    if (threadIdx.x < 32) v = warp_max(sh[threadIdx.x]);
    return v;
}
__device__ __forceinline__ float blk_sum_f(float v, float* sh) {
    v = warp_sum(v);
    __syncthreads();
    if ((threadIdx.x & 31) == 0) sh[threadIdx.x >> 5] = v;
    __syncthreads();
    if (threadIdx.x < 32) v = warp_sum(sh[threadIdx.x]);
    return v;
}
__device__ __forceinline__ unsigned long long blk_max_u64(unsigned long long v, unsigned long long* sh) {
    v = warp_max_u64(v);
    __syncthreads();
    if ((threadIdx.x & 31) == 0) sh[threadIdx.x >> 5] = v;
    __syncthreads();
    if (threadIdx.x < 32) v = warp_max_u64(sh[threadIdx.x]);
    return v;
}

__global__ void __launch_bounds__(NTHREADS, 1)
ranking_kernel(const float* __restrict__ pred,
               const float* __restrict__ E,
               float* __restrict__ out,
               int nb)
{
    __shared__ float               v_s[DIM];        // selected row, pre-scaled by inv_norm[idx]
    __shared__ unsigned long long  sh_u64[32];
    __shared__ float               sh_f[32];
    __shared__ int                 sh_idx;
    __shared__ float               sh_bc;
    __shared__ float               sh_sims[KSEL][KSEL];

    const int tid      = threadIdx.x;
    const int bid      = blockIdx.x;
    const int lid      = tid & 31;
    const int wid      = tid >> 5;
    const int gthreads = nb * NTHREADS;
    const int gtid     = bid * NTHREADS + tid;
    const int gw       = gtid >> 5;          // global warp id
    const int nwarps   = gthreads >> 5;

    // ---------------- A1a: max(predictions) ----------------
    float m = -INFINITY;
    for (int i = gtid; i < NITEMS; i += gthreads) m = fmaxf(m, pred[i]);
    m = blk_max_f(m, sh_f);
    if (tid == 0) g_pmax_part[bid] = m;
    grid_sync(nb);

    // ---------------- A1b: sum(exp(p - pmax)) ----------------
    float pm = (tid < nb) ? __ldcg(&g_pmax_part[tid]) : -INFINITY;
    pm = blk_max_f(pm, sh_f);
    if (tid == 0) sh_bc = pm;
    __syncthreads();
    const float pmax = sh_bc;

    float s = 0.f;
    for (int i = gtid; i < NITEMS; i += gthreads) s += expf(pred[i] - pmax);
    s = blk_sum_f(s, sh_f);
    if (tid == 0) g_psum_part[bid] = s;
    grid_sync(nb);

    // ---------------- A2: rel, inv-norms, init max_sim, argmax for t=0 ----------------
    float ps = (tid < nb) ? __ldcg(&g_psum_part[tid]) : 0.f;
    ps = blk_sum_f(ps, sh_f);
    if (tid == 0) sh_bc = ps;
    __syncthreads();
    const float invS = 1.0f / sh_bc;

    {
        unsigned long long best = 0ull;
        for (int row = gw; row < NITEMS; row += nwarps) {
            const float4* Er = reinterpret_cast<const float4*>(E) + (size_t)row * (DIM / 4);
            float ss = 0.f;
            #pragma unroll
            for (int j = 0; j < 4; j++) {
                float4 a = Er[j * 32 + lid];
                ss += a.x * a.x + a.y * a.y + a.z * a.z + a.w * a.w;
            }
            ss = warp_sum(ss);
            if (lid == 0) {
                float inv = 1.0f / (sqrtf(ss) + 1e-12f);
                g_inv[row] = inv;
                float r = expf(pred[row] - pmax) * invS;
                g_rel[row] = r;
                g_maxsim[row] = 0.f;
                unsigned long long p = pack_si(r, row);   // score_0 = rel (max_sim = 0)
                if (p > best) best = p;
            }
        }
        best = blk_max_u64(best, sh_u64);
        if (tid == 0) g_best[0][bid] = best;
    }
    grid_sync(nb);

    // ---------------- greedy loop ----------------
    float decay_t = 1.0f;
    for (int t = 0; t < KSEL; t++) {
        // winner of iteration t from double-buffered partials (L1-bypassing loads)
        unsigned long long w = (tid < nb) ? __ldcg(&g_best[t & 1][tid]) : 0ull;
        w = blk_max_u64(w, sh_u64);
        if (tid == 0) sh_idx = (int)(~(unsigned int)(w & 0xFFFFFFFFull));
        __syncthreads();
        const int idx = sh_idx;

        if (bid == 0 && tid == 0) {
            g_err[t] = g_rel[idx] * decay_t;
            g_sel[t] = idx;
        }

        if (t < KSEL - 1) {
            // broadcast selected row into SMEM, pre-scaled by its inv-norm
            const float inv_idx = g_inv[idx];
            if (tid < DIM / 4) {
                float4 v = reinterpret_cast<const float4*>(E)[(size_t)idx * (DIM / 4) + tid];
                v.x *= inv_idx; v.y *= inv_idx; v.z *= inv_idx; v.w *= inv_idx;
                reinterpret_cast<float4*>(v_s)[tid] = v;
            }
            __syncthreads();

            const float decay_next = decay_t * DECAYF;
            unsigned long long best = 0ull;
            for (int row = gw; row < NITEMS; row += nwarps) {
                const float4* Er = reinterpret_cast<const float4*>(E) + (size_t)row * (DIM / 4);
                const float4* Vs = reinterpret_cast<const float4*>(v_s);
                float acc = 0.f;
                #pragma unroll
                for (int j = 0; j < 4; j++) {
                    float4 a = Er[j * 32 + lid];
                    float4 b = Vs[j * 32 + lid];
                    acc += a.x * b.x + a.y * b.y + a.z * b.z + a.w * b.w;
                }
                acc = warp_sum(acc);
                if (lid == 0) {
                    float ms;
                    if (row == idx) {
                        ms = 1e30f;                       // mask the freshly selected row
                    } else {
                        float sim = acc * g_inv[row];
                        ms = fmaxf(g_maxsim[row], sim);
                    }
                    g_maxsim[row] = ms;
                    float score = decay_next * g_rel[row] - LAMBDA * ms;
                    unsigned long long p = pack_si(score, row);
                    if (p > best) best = p;
                }
            }
            best = blk_max_u64(best, sh_u64);
            if (tid == 0) g_best[(t + 1) & 1][bid] = best;
            grid_sync(nb);
        }
        decay_t *= DECAYF;
    }

    // ---------------- final: err sum + mmr over selected 16x16 (block 0 only) ----------------
    if (bid == 0) {
        __syncthreads();
        for (int p = wid; p < KSEL * KSEL; p += 32) {
            int a = p >> 4, b = p & 15;
            int ia = g_sel[a], ib = g_sel[b];
            const float4* Ea = reinterpret_cast<const float4*>(E) + (size_t)ia * (DIM / 4);
            const float4* Eb = reinterpret_cast<const float4*>(E) + (size_t)ib * (DIM / 4);
            float acc = 0.f;
            #pragma unroll
            for (int j = 0; j < 4; j++) {
                float4 x = Ea[j * 32 + lid];
                float4 y = Eb[j * 32 + lid];
                acc += x.x * y.x + x.y * y.y + x.z * y.z + x.w * y.w;
            }
            acc = warp_sum(acc);
            if (lid == 0) sh_sims[a][b] = acc * g_inv[ia] * g_inv[ib];
        }
        __syncthreads();
        if (tid == 0) {
            float se = 0.f;
            #pragma unroll
            for (int t = 0; t < KSEL; t++) se += g_err[t];
            float sm = 0.f;
            #pragma unroll
            for (int a = 0; a < KSEL; a++) {
                float mx = -INFINITY;
                #pragma unroll
                for (int b = 0; b < KSEL; b++) mx = fmaxf(mx, sh_sims[a][b]);
                sm += mx;
            }
            out[0] = -se - LAMBDA * sm;   // err_loss + LAMBDA * mmr_loss
        }
    }
}

extern "C" void kernel_launch(void* const* d_in, const int* in_sizes, int n_in,
                              void* d_out, int out_size) {
    (void)in_sizes; (void)n_in; (void)out_size;
    const float* pred = (const float*)d_in[0];
    const float* E    = (const float*)d_in[5];   // explanation_embeddings [32768, 512]
    float* out        = (float*)d_out;

    int dev = 0;
    cudaGetDevice(&dev);
    int nsm = 0;
    cudaDeviceGetAttribute(&nsm, cudaDevAttrMultiProcessorCount, dev);
    if (nsm <= 0) nsm = 148;
    if (nsm > MAXB) nsm = MAXB;

    ranking_kernel<<<nsm, NTHREADS>>>(pred, E, out, nsm);
}

// round 3
// speedup vs baseline: 1.8641x; 1.8641x over previous
#include <cuda_runtime.h>
#include <cuda_fp16.h>
#include <math.h>

#define NITEMS   32768
#define DIM      512
#define KSEL     16
#define LAMBDA   0.5f
#define DECAYF   0.85f
#define NTHREADS 1024
#define MAXB     512
#define RPW      7          // rows per warp (148*32 warps * 7 = 33152 >= 32768)

// ---------------- device scratch (no allocations allowed) ----------------
__device__ __align__(128) __half  g_En[NITEMS * DIM];   // normalized embeddings, fp16 (32 MB)
__device__ __align__(128) float2  g_meta[NITEMS];       // (rel, max_sim); 1e30 = masked
__device__ float               g_pmax_part[MAXB];
__device__ float               g_psum_part[MAXB];
__device__ unsigned long long  g_best[2][MAXB];         // double-buffered argmax partials
__device__ float               g_err[KSEL];
__device__ int                 g_sel[KSEL];
__device__ unsigned int        g_bar;                   // monotonic grid barrier

// ---------------- monotonic grid barrier ----------------
__device__ __forceinline__ void grid_sync(int nb) {
    __threadfence();            // every thread publishes its stores before arriving
    __syncthreads();
    if (threadIdx.x == 0) {
        unsigned int ticket = atomicAdd(&g_bar, 1u) + 1u;
        unsigned int target = ((ticket + (unsigned)nb - 1u) / (unsigned)nb) * (unsigned)nb;
        while (*((volatile unsigned int*)&g_bar) < target) { }
        __threadfence();
    }
    __syncthreads();
}

// order-preserving float->u32; low 32 bits = ~row so ties pick the SMALLEST row
__device__ __forceinline__ unsigned long long pack_si(float s, int row) {
    unsigned int b = __float_as_uint(s);
    unsigned int e = (b & 0x80000000u) ? ~b : (b | 0x80000000u);
    return ((unsigned long long)e << 32) | (unsigned int)(~row);
}

__device__ __forceinline__ float warp_sum_xor(float v) {
    #pragma unroll
    for (int o = 16; o > 0; o >>= 1) v += __shfl_xor_sync(0xffffffffu, v, o);
    return v;
}
__device__ __forceinline__ float warp_max(float v) {
    #pragma unroll
    for (int o = 16; o > 0; o >>= 1) v = fmaxf(v, __shfl_down_sync(0xffffffffu, v, o));
    return v;
}
__device__ __forceinline__ unsigned long long warp_max_u64(unsigned long long v) {
    #pragma unroll
    for (int o = 16; o > 0; o >>= 1) {
        unsigned long long u = __shfl_down_sync(0xffffffffu, v, o);
        if (u > v) v = u;
    }
    return v;
}
__device__ __forceinline__ float blk_max_f(float v, float* sh) {
    v = warp_max(v);
    __syncthreads();
    if ((threadIdx.x & 31) == 0) sh[threadIdx.x >> 5] = v;
    __syncthreads();
    if (threadIdx.x < 32) v = warp_max(sh[threadIdx.x]);
    return v;
}
__device__ __forceinline__ float blk_sum_f(float v, float* sh) {
    #pragma unroll
    for (int o = 16; o > 0; o >>= 1) v += __shfl_down_sync(0xffffffffu, v, o);
    __syncthreads();
    if ((threadIdx.x & 31) == 0) sh[threadIdx.x >> 5] = v;
    __syncthreads();
    if (threadIdx.x < 32) {
        v = sh[threadIdx.x];
        #pragma unroll
        for (int o = 16; o > 0; o >>= 1) v += __shfl_down_sync(0xffffffffu, v, o);
    }
    return v;
}
__device__ __forceinline__ unsigned long long blk_max_u64(unsigned long long v, unsigned long long* sh) {
    v = warp_max_u64(v);
    __syncthreads();
    if ((threadIdx.x & 31) == 0) sh[threadIdx.x >> 5] = v;
    __syncthreads();
    if (threadIdx.x < 32) v = warp_max_u64(sh[threadIdx.x]);
    return v;
}

// GEMV over CNT rows starting at rbase+START; fills *mysim for lanes START..START+CNT-1
template<int CNT>
__device__ __forceinline__ void gemv_group(int rbase, int start, int lid,
                                           const float (&vv)[16], float* mysim) {
    const uint4* Eh4 = reinterpret_cast<const uint4*>(g_En);
    float acc[CNT];
    #pragma unroll
    for (int i = 0; i < CNT; i++) acc[i] = 0.f;
    #pragma unroll
    for (int j = 0; j < 2; j++) {
        uint4 a[CNT];
        #pragma unroll
        for (int i = 0; i < CNT; i++) {
            int row = rbase + start + i;
            row = (row < NITEMS) ? row : (NITEMS - 1);       // clamp: harmless dup load
            a[i] = Eh4[(size_t)row * 64 + j * 32 + lid];
        }
        #pragma unroll
        for (int i = 0; i < CNT; i++) {
            const __half2* h = reinterpret_cast<const __half2*>(&a[i]);
            #pragma unroll
            for (int q = 0; q < 4; q++) {
                float2 f = __half22float2(h[q]);
                acc[i] = fmaf(f.x, vv[j * 8 + 2 * q],     acc[i]);
                acc[i] = fmaf(f.y, vv[j * 8 + 2 * q + 1], acc[i]);
            }
        }
    }
    #pragma unroll
    for (int o = 16; o > 0; o >>= 1) {
        #pragma unroll
        for (int i = 0; i < CNT; i++) acc[i] += __shfl_xor_sync(0xffffffffu, acc[i], o);
    }
    #pragma unroll
    for (int i = 0; i < CNT; i++) if (lid == start + i) *mysim = acc[i];
}

__global__ void __launch_bounds__(NTHREADS, 1)
ranking_kernel(const float* __restrict__ pred,
               const float* __restrict__ E,
               float* __restrict__ out,
               int nb)
{
    __shared__ unsigned long long sh_u64[32];
    __shared__ float              sh_f[32];
    __shared__ int                sh_idx;
    __shared__ float              sh_bc;
    __shared__ float              sh_sims[KSEL][KSEL];

    const int tid   = threadIdx.x;
    const int bid   = blockIdx.x;
    const int lid   = tid & 31;
    const int wid   = tid >> 5;
    const int gw    = bid * 32 + wid;
    const int rbase = gw * RPW;
    const int gthreads = nb * NTHREADS;
    const int gtid     = bid * NTHREADS + tid;

    // ---------------- A1a: max(predictions) ----------------
    float m = -INFINITY;
    for (int i = gtid; i < NITEMS; i += gthreads) m = fmaxf(m, pred[i]);
    m = blk_max_f(m, sh_f);
    if (tid == 0) g_pmax_part[bid] = m;
    grid_sync(nb);

    // ---------------- A1b: sum(exp(p - pmax)) ----------------
    float pm = (tid < nb) ? __ldcg(&g_pmax_part[tid]) : -INFINITY;
    pm = blk_max_f(pm, sh_f);
    if (tid == 0) sh_bc = pm;
    __syncthreads();
    const float pmax = sh_bc;

    float s = 0.f;
    for (int i = gtid; i < NITEMS; i += gthreads) s += expf(pred[i] - pmax);
    s = blk_sum_f(s, sh_f);
    if (tid == 0) g_psum_part[bid] = s;
    grid_sync(nb);

    float ps = (tid < nb) ? __ldcg(&g_psum_part[tid]) : 0.f;
    ps = blk_sum_f(ps, sh_f);
    if (tid == 0) sh_bc = ps;
    __syncthreads();
    const float invS = 1.0f / sh_bc;

    // ---------------- A2: normalize -> fp16, rel, init meta, argmax t=0 ----------------
    {
        unsigned long long best = 0ull;
        #pragma unroll
        for (int i = 0; i < RPW; i++) {
            int row = rbase + i;
            if (row < NITEMS) {
                const float4* Er = reinterpret_cast<const float4*>(E) + (size_t)row * (DIM / 4);
                float4 av[4];
                #pragma unroll
                for (int j = 0; j < 4; j++) av[j] = Er[j * 32 + lid];
                float ss = 0.f;
                #pragma unroll
                for (int j = 0; j < 4; j++)
                    ss += av[j].x * av[j].x + av[j].y * av[j].y + av[j].z * av[j].z + av[j].w * av[j].w;
                ss = warp_sum_xor(ss);
                const float inv = 1.0f / (sqrtf(ss) + 1e-12f);

                uint2* Eh2 = reinterpret_cast<uint2*>(g_En) + (size_t)row * (DIM / 4);
                #pragma unroll
                for (int j = 0; j < 4; j++) {
                    __half2 h0 = __floats2half2_rn(av[j].x * inv, av[j].y * inv);
                    __half2 h1 = __floats2half2_rn(av[j].z * inv, av[j].w * inv);
                    uint2 u;
                    u.x = *reinterpret_cast<unsigned*>(&h0);
                    u.y = *reinterpret_cast<unsigned*>(&h1);
                    Eh2[j * 32 + lid] = u;
                }
                if (lid == 0) {
                    float r = expf(pred[row] - pmax) * invS;
                    g_meta[row] = make_float2(r, 0.f);
                    unsigned long long p = pack_si(r, row);   // score_0 = rel
                    if (p > best) best = p;
                }
            }
        }
        best = blk_max_u64(best, sh_u64);
        if (tid == 0) g_best[0][bid] = best;
    }
    grid_sync(nb);

    const bool mine  = (lid < RPW) && (rbase + lid < NITEMS);
    const int  myrow = rbase + lid;

    // ---------------- greedy loop ----------------
    float decay_t = 1.0f;
    for (int t = 0; t < KSEL; t++) {
        unsigned long long w = (tid < nb) ? __ldcg(&g_best[t & 1][tid]) : 0ull;
        w = blk_max_u64(w, sh_u64);
        if (tid == 0) sh_idx = (int)(~(unsigned int)(w & 0xFFFFFFFFull));
        __syncthreads();
        const int idx = sh_idx;

        if (bid == 0 && tid == 0) {
            g_err[t] = __ldcg(&g_meta[idx].x) * decay_t;
            g_sel[t] = idx;
        }

        if (t < KSEL - 1) {
            // v vector (normalized, fp16 -> fp32 regs), same lane layout as rows
            float vv[16];
            const uint4* Vh = reinterpret_cast<const uint4*>(g_En) + (size_t)idx * 64;
            #pragma unroll
            for (int j = 0; j < 2; j++) {
                uint4 u = Vh[j * 32 + lid];
                const __half2* h = reinterpret_cast<const __half2*>(&u);
                #pragma unroll
                for (int q = 0; q < 4; q++) {
                    float2 f = __half22float2(h[q]);
                    vv[j * 8 + 2 * q]     = f.x;
                    vv[j * 8 + 2 * q + 1] = f.y;
                }
            }
            // parallel metadata prefetch (lane i owns row rbase+i)
            float myrel = 0.f, myms = 0.f;
            if (mine) { float2 mm = g_meta[myrow]; myrel = mm.x; myms = mm.y; }

            float mysim = 0.f;
            gemv_group<4>(rbase, 0, lid, vv, &mysim);
            gemv_group<3>(rbase, 4, lid, vv, &mysim);

            unsigned long long best = 0ull;
            const float decay_next = decay_t * DECAYF;
            if (mine) {
                float ms = (myrow == idx) ? 1e30f : fmaxf(myms, mysim);
                g_meta[myrow].y = ms;
                float score = decay_next * myrel - LAMBDA * ms;
                best = pack_si(score, myrow);
            }
            best = blk_max_u64(best, sh_u64);
            if (tid == 0) g_best[(t + 1) & 1][bid] = best;
            grid_sync(nb);
        }
        decay_t *= DECAYF;
    }

    // ---------------- final: err sum + mmr over selected 16x16 (block 0) ----------------
    if (bid == 0) {
        __syncthreads();
        for (int p = wid; p < KSEL * KSEL; p += 32) {
            int a = p >> 4, b = p & 15;
            int ia = g_sel[a], ib = g_sel[b];
            const uint4* Ea = reinterpret_cast<const uint4*>(g_En) + (size_t)ia * 64;
            const uint4* Eb = reinterpret_cast<const uint4*>(g_En) + (size_t)ib * 64;
            float acc = 0.f;
            #pragma unroll
            for (int j = 0; j < 2; j++) {
                uint4 x = Ea[j * 32 + lid];
                uint4 y = Eb[j * 32 + lid];
                const __half2* hx = reinterpret_cast<const __half2*>(&x);
                const __half2* hy = reinterpret_cast<const __half2*>(&y);
                #pragma unroll
                for (int q = 0; q < 4; q++) {
                    float2 fx = __half22float2(hx[q]);
                    float2 fy = __half22float2(hy[q]);
                    acc = fmaf(fx.x, fy.x, acc);
                    acc = fmaf(fx.y, fy.y, acc);
                }
            }
            acc = warp_sum_xor(acc);
            if (lid == 0) sh_sims[a][b] = acc;
        }
        __syncthreads();
        if (tid == 0) {
            float se = 0.f;
            #pragma unroll
            for (int t = 0; t < KSEL; t++) se += g_err[t];
            float sm = 0.f;
            #pragma unroll
            for (int a = 0; a < KSEL; a++) {
                float mx = -INFINITY;
                #pragma unroll
                for (int b = 0; b < KSEL; b++) mx = fmaxf(mx, sh_sims[a][b]);
                sm += mx;
            }
            out[0] = -se - LAMBDA * sm;
        }
    }
}

extern "C" void kernel_launch(void* const* d_in, const int* in_sizes, int n_in,
                              void* d_out, int out_size) {
    (void)in_sizes; (void)n_in; (void)out_size;
    const float* pred = (const float*)d_in[0];
    const float* E    = (const float*)d_in[5];   // explanation_embeddings [32768, 512]
    float* out        = (float*)d_out;

    int dev = 0;
    cudaGetDevice(&dev);
    int nsm = 0;
    cudaDeviceGetAttribute(&nsm, cudaDevAttrMultiProcessorCount, dev);
    if (nsm <= 0) nsm = 148;
    if (nsm > MAXB) nsm = MAXB;

    ranking_kernel<<<nsm, NTHREADS>>>(pred, E, out, nsm);
}

// round 4
// speedup vs baseline: 2.0839x; 1.1180x over previous
#include <cuda_runtime.h>
#include <cuda_fp16.h>
#include <math.h>

#define NITEMS   32768
#define DIM      512
#define KSEL     16
#define LAMBDA   0.5f
#define DECAYF   0.85f
#define NTHREADS 1024
#define MAXB     512
#define RPW      7          // rows per warp (148*32*7 = 33152 >= 32768)

// ---------------- device scratch (no allocations allowed) ----------------
__device__ __align__(128) __half  g_En[NITEMS * DIM];   // normalized embeddings, fp16 (32 MB)
__device__ __align__(128) float   g_rel[NITEMS];        // softmax(pred), written once in prologue
__device__ float               g_pmax_part[MAXB];
__device__ float               g_psum_part[MAXB];
__device__ unsigned long long  g_best[2][MAXB];         // double-buffered argmax partials
__device__ float               g_err[KSEL];
__device__ int                 g_sel[KSEL];
__device__ unsigned int        g_bar;                   // monotonic grid barrier

// ---------------- monotonic grid barrier (t0-only fence; cumulative via syncthreads) ----
__device__ __forceinline__ void grid_sync(int nb) {
    __syncthreads();
    if (threadIdx.x == 0) {
        __threadfence();
        unsigned int ticket = atomicAdd(&g_bar, 1u) + 1u;
        unsigned int target = ((ticket + (unsigned)nb - 1u) / (unsigned)nb) * (unsigned)nb;
        while (*((volatile unsigned int*)&g_bar) < target) { }
        __threadfence();
    }
    __syncthreads();
}

// order-preserving float->u32; low 32 bits = ~row so ties pick the SMALLEST row
__device__ __forceinline__ unsigned long long pack_si(float s, int row) {
    unsigned int b = __float_as_uint(s);
    unsigned int e = (b & 0x80000000u) ? ~b : (b | 0x80000000u);
    return ((unsigned long long)e << 32) | (unsigned int)(~row);
}

__device__ __forceinline__ float warp_sum_xor(float v) {
    #pragma unroll
    for (int o = 16; o > 0; o >>= 1) v += __shfl_xor_sync(0xffffffffu, v, o);
    return v;
}
__device__ __forceinline__ float warp_max(float v) {
    #pragma unroll
    for (int o = 16; o > 0; o >>= 1) v = fmaxf(v, __shfl_down_sync(0xffffffffu, v, o));
    return v;
}
__device__ __forceinline__ unsigned long long warp_max_u64(unsigned long long v) {
    #pragma unroll
    for (int o = 16; o > 0; o >>= 1) {
        unsigned long long u = __shfl_down_sync(0xffffffffu, v, o);
        if (u > v) v = u;
    }
    return v;
}
__device__ __forceinline__ float blk_max_f(float v, float* sh) {
    v = warp_max(v);
    __syncthreads();
    if ((threadIdx.x & 31) == 0) sh[threadIdx.x >> 5] = v;
    __syncthreads();
    if (threadIdx.x < 32) v = warp_max(sh[threadIdx.x]);
    return v;
}
__device__ __forceinline__ float blk_sum_f(float v, float* sh) {
    #pragma unroll
    for (int o = 16; o > 0; o >>= 1) v += __shfl_down_sync(0xffffffffu, v, o);
    __syncthreads();
    if ((threadIdx.x & 31) == 0) sh[threadIdx.x >> 5] = v;
    __syncthreads();
    if (threadIdx.x < 32) {
        v = sh[threadIdx.x];
        #pragma unroll
        for (int o = 16; o > 0; o >>= 1) v += __shfl_down_sync(0xffffffffu, v, o);
    }
    return v;
}
__device__ __forceinline__ unsigned long long blk_max_u64(unsigned long long v, unsigned long long* sh) {
    v = warp_max_u64(v);
    __syncthreads();
    if ((threadIdx.x & 31) == 0) sh[threadIdx.x >> 5] = v;
    __syncthreads();
    if (threadIdx.x < 32) v = warp_max_u64(sh[threadIdx.x]);
    return v;
}

// HFMA2 GEMV over CNT rows starting at rbase+start; lane (start+i) receives row i's dot in *mysim.
// fp16 accumulation limited to 4-term chains (error ~1e-5 abs), cross-chain + cross-lane in fp32.
template<int CNT>
__device__ __forceinline__ void gemv_rows(int rbase, int start, int lid,
                                          const __half2 (&vh)[8], float* mysim) {
    const uint4* Eh4 = reinterpret_cast<const uint4*>(g_En);
    uint4 a0[CNT], a1[CNT];
    #pragma unroll
    for (int i = 0; i < CNT; i++) {
        int row = rbase + start + i;
        row = (row < NITEMS) ? row : (NITEMS - 1);          // clamp: harmless dup
        a0[i] = Eh4[(size_t)row * 64 + lid];
        a1[i] = Eh4[(size_t)row * 64 + 32 + lid];
    }
    float f[CNT];
    #pragma unroll
    for (int i = 0; i < CNT; i++) {
        const __half2* h0 = reinterpret_cast<const __half2*>(&a0[i]);
        const __half2* h1 = reinterpret_cast<const __half2*>(&a1[i]);
        __half2 acc_a = __hmul2(h0[0], vh[0]);
        __half2 acc_b = __hmul2(h0[1], vh[1]);
        acc_a = __hfma2(h0[2], vh[2], acc_a);
        acc_b = __hfma2(h0[3], vh[3], acc_b);
        acc_a = __hfma2(h1[0], vh[4], acc_a);
        acc_b = __hfma2(h1[1], vh[5], acc_b);
        acc_a = __hfma2(h1[2], vh[6], acc_a);
        acc_b = __hfma2(h1[3], vh[7], acc_b);
        float2 fa = __half22float2(acc_a);
        float2 fb = __half22float2(acc_b);
        f[i] = (fa.x + fa.y) + (fb.x + fb.y);
    }
    #pragma unroll
    for (int o = 16; o > 0; o >>= 1) {
        #pragma unroll
        for (int i = 0; i < CNT; i++) f[i] += __shfl_xor_sync(0xffffffffu, f[i], o);
    }
    #pragma unroll
    for (int i = 0; i < CNT; i++) if (lid == start + i) *mysim = f[i];
}

__global__ void __launch_bounds__(NTHREADS, 1)
ranking_kernel(const float* __restrict__ pred,
               const float* __restrict__ E,
               float* __restrict__ out,
               int nb)
{
    __shared__ unsigned long long sh_u64[32];
    __shared__ float              sh_f[32];
    __shared__ int                sh_idx;
    __shared__ float              sh_bc;
    __shared__ float              sh_sims[KSEL][KSEL];

    const int tid   = threadIdx.x;
    const int bid   = blockIdx.x;
    const int lid   = tid & 31;
    const int wid   = tid >> 5;
    const int gw    = bid * 32 + wid;
    const int rbase = gw * RPW;
    const int gthreads = nb * NTHREADS;
    const int gtid     = bid * NTHREADS + tid;

    // ---------------- A1a: max(predictions) ----------------
    float m = -INFINITY;
    for (int i = gtid; i < NITEMS; i += gthreads) m = fmaxf(m, pred[i]);
    m = blk_max_f(m, sh_f);
    if (tid == 0) g_pmax_part[bid] = m;
    grid_sync(nb);

    // ---------------- A1b: sum(exp(p - pmax)) ----------------
    float pm = (tid < nb) ? __ldcg(&g_pmax_part[tid]) : -INFINITY;
    pm = blk_max_f(pm, sh_f);
    if (tid == 0) sh_bc = pm;
    __syncthreads();
    const float pmax = sh_bc;

    float s = 0.f;
    for (int i = gtid; i < NITEMS; i += gthreads) s += expf(pred[i] - pmax);
    s = blk_sum_f(s, sh_f);
    if (tid == 0) g_psum_part[bid] = s;
    grid_sync(nb);

    float ps = (tid < nb) ? __ldcg(&g_psum_part[tid]) : 0.f;
    ps = blk_sum_f(ps, sh_f);
    if (tid == 0) sh_bc = ps;
    __syncthreads();
    const float invS = 1.0f / sh_bc;

    // lane l of this warp owns row rbase+l forever; rel & max_sim live in registers
    const bool  mine  = (lid < RPW) && (rbase + lid < NITEMS);
    const int   myrow = rbase + lid;
    float myrel = 0.f, myms = 0.f;
    if (mine) {
        myrel = expf(pred[myrow] - pmax) * invS;
        g_rel[myrow] = myrel;                         // for block0's err lookup
    }

    // ---------------- A2: normalize -> fp16 (software-pipelined loads), argmax t=0 ----------------
    {
        const float4* Erow = reinterpret_cast<const float4*>(E) + (size_t)rbase * (DIM / 4);
        float4 cur[4];
        bool have = (rbase < NITEMS);
        if (have) {
            #pragma unroll
            for (int j = 0; j < 4; j++) cur[j] = Erow[j * 32 + lid];
        }
        #pragma unroll
        for (int i = 0; i < RPW; i++) {
            int row = rbase + i;
            float4 nxt[4];
            bool have_n = (i + 1 < RPW) && (row + 1 < NITEMS);
            if (have_n) {
                const float4* Er2 = Erow + (size_t)(i + 1) * (DIM / 4);
                #pragma unroll
                for (int j = 0; j < 4; j++) nxt[j] = Er2[j * 32 + lid];
            }
            if (row < NITEMS) {
                float ss = 0.f;
                #pragma unroll
                for (int j = 0; j < 4; j++)
                    ss += cur[j].x * cur[j].x + cur[j].y * cur[j].y
                        + cur[j].z * cur[j].z + cur[j].w * cur[j].w;
                ss = warp_sum_xor(ss);
                const float inv = 1.0f / (sqrtf(ss) + 1e-12f);
                uint2* Eh2 = reinterpret_cast<uint2*>(g_En) + (size_t)row * (DIM / 4);
                #pragma unroll
                for (int j = 0; j < 4; j++) {
                    __half2 h0 = __floats2half2_rn(cur[j].x * inv, cur[j].y * inv);
                    __half2 h1 = __floats2half2_rn(cur[j].z * inv, cur[j].w * inv);
                    uint2 u;
                    u.x = *reinterpret_cast<unsigned*>(&h0);
                    u.y = *reinterpret_cast<unsigned*>(&h1);
                    Eh2[j * 32 + lid] = u;
                }
            }
            #pragma unroll
            for (int j = 0; j < 4; j++) cur[j] = nxt[j];
        }
        unsigned long long best = mine ? pack_si(myrel, myrow) : 0ull;  // score_0 = rel
        best = blk_max_u64(best, sh_u64);
        if (tid == 0) g_best[0][bid] = best;
    }
    grid_sync(nb);

    // ---------------- greedy loop ----------------
    float decay_t = 1.0f;
    for (int t = 0; t < KSEL; t++) {
        unsigned long long w = (tid < nb) ? __ldcg(&g_best[t & 1][tid]) : 0ull;
        w = blk_max_u64(w, sh_u64);
        if (tid == 0) sh_idx = (int)(~(unsigned int)(w & 0xFFFFFFFFull));
        __syncthreads();
        const int idx = sh_idx;

        if (bid == 0 && tid == 0) {
            g_err[t] = __ldcg(&g_rel[idx]) * decay_t;
            g_sel[t] = idx;
        }

        if (t < KSEL - 1) {
            // v vector (normalized fp16) kept as half2 registers, same lane layout as rows
            const uint4* Vh = reinterpret_cast<const uint4*>(g_En) + (size_t)idx * 64;
            uint4 v0 = Vh[lid];
            uint4 v1 = Vh[32 + lid];
            __half2 vh[8];
            {
                const __half2* p0 = reinterpret_cast<const __half2*>(&v0);
                const __half2* p1 = reinterpret_cast<const __half2*>(&v1);
                #pragma unroll
                for (int q = 0; q < 4; q++) { vh[q] = p0[q]; vh[4 + q] = p1[q]; }
            }

            float mysim = 0.f;
            gemv_rows<4>(rbase, 0, lid, vh, &mysim);
            gemv_rows<3>(rbase, 4, lid, vh, &mysim);

            unsigned long long best = 0ull;
            const float decay_next = decay_t * DECAYF;
            if (mine) {
                myms = (myrow == idx) ? 1e30f : fmaxf(myms, mysim);
                float score = decay_next * myrel - LAMBDA * myms;
                best = pack_si(score, myrow);
            }
            best = blk_max_u64(best, sh_u64);
            if (tid == 0) g_best[(t + 1) & 1][bid] = best;
            grid_sync(nb);
        }
        decay_t *= DECAYF;
    }

    // ---------------- final: err sum + mmr over selected 16x16 (block 0) ----------------
    if (bid == 0) {
        __syncthreads();
        for (int p = wid; p < KSEL * KSEL; p += 32) {
            int a = p >> 4, b = p & 15;
            int ia = g_sel[a], ib = g_sel[b];
            const uint4* Ea = reinterpret_cast<const uint4*>(g_En) + (size_t)ia * 64;
            const uint4* Eb = reinterpret_cast<const uint4*>(g_En) + (size_t)ib * 64;
            float acc = 0.f;
            #pragma unroll
            for (int j = 0; j < 2; j++) {
                uint4 x = Ea[j * 32 + lid];
                uint4 y = Eb[j * 32 + lid];
                const __half2* hx = reinterpret_cast<const __half2*>(&x);
                const __half2* hy = reinterpret_cast<const __half2*>(&y);
                #pragma unroll
                for (int q = 0; q < 4; q++) {
                    float2 fx = __half22float2(hx[q]);
                    float2 fy = __half22float2(hy[q]);
                    acc = fmaf(fx.x, fy.x, acc);
                    acc = fmaf(fx.y, fy.y, acc);
                }
            }
            acc = warp_sum_xor(acc);
            if (lid == 0) sh_sims[a][b] = acc;
        }
        __syncthreads();
        if (tid == 0) {
            float se = 0.f;
            #pragma unroll
            for (int t = 0; t < KSEL; t++) se += g_err[t];
            float sm = 0.f;
            #pragma unroll
            for (int a = 0; a < KSEL; a++) {
                float mx = -INFINITY;
                #pragma unroll
                for (int b = 0; b < KSEL; b++) mx = fmaxf(mx, sh_sims[a][b]);
                sm += mx;
            }
            out[0] = -se - LAMBDA * sm;
        }
    }
}

extern "C" void kernel_launch(void* const* d_in, const int* in_sizes, int n_in,
                              void* d_out, int out_size) {
    (void)in_sizes; (void)n_in; (void)out_size;
    const float* pred = (const float*)d_in[0];
    const float* E    = (const float*)d_in[5];   // explanation_embeddings [32768, 512]
    float* out        = (float*)d_out;

    int dev = 0;
    cudaGetDevice(&dev);
    int nsm = 0;
    cudaDeviceGetAttribute(&nsm, cudaDevAttrMultiProcessorCount, dev);
    if (nsm <= 0) nsm = 148;
    if (nsm > MAXB) nsm = MAXB;

    ranking_kernel<<<nsm, NTHREADS>>>(pred, E, out, nsm);
}

// round 5
// speedup vs baseline: 2.2964x; 1.1020x over previous
#include <cuda_runtime.h>
#include <cuda_fp16.h>
#include <math.h>

#define NITEMS   32768
#define DIM      512
#define KSEL     16
#define LAMBDA   0.5f
#define DECAYF   0.85f
#define NTHREADS 1024
#define MAXB     512
#define RPW      7                      // rows per warp
#define RPB      (32 * RPW)             // 224 rows per block
#define SMEM_DYN (RPB * DIM * 2)        // 229376 B of fp16 rows

// ---------------- device scratch (no allocations allowed) ----------------
__device__ __align__(128) __half  g_En[NITEMS * DIM];   // normalized embeddings, fp16 (32 MB)
__device__ __align__(128) float   g_rel[NITEMS];        // softmax(pred)
__device__ float               g_m_part[MAXB];          // online-softmax partial max
__device__ float               g_s_part[MAXB];          // online-softmax partial sum
__device__ unsigned long long  g_best[2][MAXB];         // double-buffered argmax partials
__device__ float               g_err[KSEL];
__device__ int                 g_sel[KSEL];
__device__ unsigned int        g_bar;                   // monotonic grid barrier

// ---------------- monotonic grid barrier ----------------
__device__ __forceinline__ void grid_sync(int nb) {
    __syncthreads();
    if (threadIdx.x == 0) {
        __threadfence();
        unsigned int ticket = atomicAdd(&g_bar, 1u) + 1u;
        unsigned int target = ((ticket + (unsigned)nb - 1u) / (unsigned)nb) * (unsigned)nb;
        while (*((volatile unsigned int*)&g_bar) < target) { }
        __threadfence();
    }
    __syncthreads();
}

// order-preserving float->u32; low 32 bits = ~row so ties pick the SMALLEST row
__device__ __forceinline__ unsigned long long pack_si(float s, int row) {
    unsigned int b = __float_as_uint(s);
    unsigned int e = (b & 0x80000000u) ? ~b : (b | 0x80000000u);
    return ((unsigned long long)e << 32) | (unsigned int)(~row);
}

__device__ __forceinline__ float warp_sum_xor(float v) {
    #pragma unroll
    for (int o = 16; o > 0; o >>= 1) v += __shfl_xor_sync(0xffffffffu, v, o);
    return v;
}
__device__ __forceinline__ unsigned long long warp_max_u64(unsigned long long v) {
    #pragma unroll
    for (int o = 16; o > 0; o >>= 1) {
        unsigned long long u = __shfl_down_sync(0xffffffffu, v, o);
        if (u > v) v = u;
    }
    return v;
}
__device__ __forceinline__ unsigned long long blk_max_u64(unsigned long long v, unsigned long long* sh) {
    v = warp_max_u64(v);
    __syncthreads();
    if ((threadIdx.x & 31) == 0) sh[threadIdx.x >> 5] = v;
    __syncthreads();
    if (threadIdx.x < 32) v = warp_max_u64(sh[threadIdx.x]);
    return v;
}
// online-softmax pair merge: (m,s) <- merge((m,s),(m2,s2)); uses finite sentinel -1e30
__device__ __forceinline__ void merge_ms(float& m, float& s, float m2, float s2) {
    float M = fmaxf(m, m2);
    s = s * expf(m - M) + s2 * expf(m2 - M);
    m = M;
}

__global__ void __launch_bounds__(NTHREADS, 1)
ranking_kernel(const float* __restrict__ pred,
               const float* __restrict__ E,
               float* __restrict__ out,
               int nb)
{
    extern __shared__ __align__(16) __half sm_rows[];   // RPB rows x 512 fp16

    __shared__ unsigned long long sh_u64[32];
    __shared__ float              sh_m[32], sh_s[32];
    __shared__ int                sh_idx;
    __shared__ float              sh_bm, sh_bs;
    __shared__ float              sh_sims[KSEL][KSEL];

    const int tid   = threadIdx.x;
    const int bid   = blockIdx.x;
    const int lid   = tid & 31;
    const int wid   = tid >> 5;
    const int rbase = (bid * 32 + wid) * RPW;          // first global row of this warp
    const int gthreads = nb * NTHREADS;
    const int gtid     = bid * NTHREADS + tid;

    // ---------------- A1: online softmax over predictions (one pass, one barrier) ----
    float m = -1e30f, s = 0.f;
    for (int i = gtid; i < NITEMS; i += gthreads) {
        float p = pred[i];
        float M = fmaxf(m, p);
        s = s * expf(m - M) + expf(p - M);
        m = M;
    }
    #pragma unroll
    for (int o = 16; o > 0; o >>= 1) {
        float m2 = __shfl_xor_sync(0xffffffffu, m, o);
        float s2 = __shfl_xor_sync(0xffffffffu, s, o);
        merge_ms(m, s, m2, s2);
    }
    __syncthreads();
    if (lid == 0) { sh_m[wid] = m; sh_s[wid] = s; }
    __syncthreads();
    if (tid < 32) {
        m = sh_m[tid]; s = sh_s[tid];
        #pragma unroll
        for (int o = 16; o > 0; o >>= 1) {
            float m2 = __shfl_xor_sync(0xffffffffu, m, o);
            float s2 = __shfl_xor_sync(0xffffffffu, s, o);
            merge_ms(m, s, m2, s2);
        }
        if (tid == 0) { g_m_part[bid] = m; g_s_part[bid] = s; }
    }
    grid_sync(nb);

    // reduce 148 partials in every block
    {
        float pm = (tid < nb) ? __ldcg(&g_m_part[tid]) : -1e30f;
        float psv = (tid < nb) ? __ldcg(&g_s_part[tid]) : 0.f;
        #pragma unroll
        for (int o = 16; o > 0; o >>= 1) {
            float m2 = __shfl_xor_sync(0xffffffffu, pm, o);
            float s2 = __shfl_xor_sync(0xffffffffu, psv, o);
            merge_ms(pm, psv, m2, s2);
        }
        __syncthreads();
        if (lid == 0) { sh_m[wid] = pm; sh_s[wid] = psv; }
        __syncthreads();
        if (tid == 0) {
            float mm = sh_m[0], ss = sh_s[0];
            #pragma unroll
            for (int w = 1; w < 32; w++) merge_ms(mm, ss, sh_m[w], sh_s[w]);
            sh_bm = mm; sh_bs = ss;
        }
        __syncthreads();
    }
    const float pmax = sh_bm;
    const float invS = 1.0f / sh_bs;

    // lane l of this warp owns row rbase+l forever; rel & max_sim live in registers
    const bool  mine  = (lid < RPW) && (rbase + lid < NITEMS);
    const int   myrow = rbase + lid;
    float myrel = 0.f, myms = 0.f;
    if (mine) {
        myrel = expf(pred[myrow] - pmax) * invS;
        g_rel[myrow] = myrel;                          // for block0's err lookup
    }

    // ---------------- A2: normalize -> fp16 into GLOBAL + SMEM, argmax t=0 ----------------
    {
        const float4* Erow = reinterpret_cast<const float4*>(E) + (size_t)rbase * (DIM / 4);
        float4 cur[4];
        if (rbase < NITEMS) {
            #pragma unroll
            for (int j = 0; j < 4; j++) cur[j] = Erow[j * 32 + lid];
        }
        #pragma unroll
        for (int i = 0; i < RPW; i++) {
            int row = rbase + i;
            float4 nxt[4];
            bool have_n = (i + 1 < RPW) && (row + 1 < NITEMS);
            if (have_n) {
                const float4* Er2 = Erow + (size_t)(i + 1) * (DIM / 4);
                #pragma unroll
                for (int j = 0; j < 4; j++) nxt[j] = Er2[j * 32 + lid];
            }
            if (row < NITEMS) {
                float ss2 = 0.f;
                #pragma unroll
                for (int j = 0; j < 4; j++)
                    ss2 += cur[j].x * cur[j].x + cur[j].y * cur[j].y
                         + cur[j].z * cur[j].z + cur[j].w * cur[j].w;
                ss2 = warp_sum_xor(ss2);
                const float inv = 1.0f / (sqrtf(ss2) + 1e-12f);
                uint2* Eg = reinterpret_cast<uint2*>(g_En) + (size_t)row * (DIM / 4);
                uint2* Es = reinterpret_cast<uint2*>(sm_rows) + (size_t)(wid * RPW + i) * (DIM / 4);
                #pragma unroll
                for (int j = 0; j < 4; j++) {
                    __half2 h0 = __floats2half2_rn(cur[j].x * inv, cur[j].y * inv);
                    __half2 h1 = __floats2half2_rn(cur[j].z * inv, cur[j].w * inv);
                    uint2 u;
                    u.x = *reinterpret_cast<unsigned*>(&h0);
                    u.y = *reinterpret_cast<unsigned*>(&h1);
                    Eg[j * 32 + lid] = u;
                    Es[j * 32 + lid] = u;
                }
            }
            #pragma unroll
            for (int j = 0; j < 4; j++) cur[j] = nxt[j];
        }
        unsigned long long best = mine ? pack_si(myrel, myrow) : 0ull;   // score_0 = rel
        best = blk_max_u64(best, sh_u64);
        if (tid == 0) g_best[0][bid] = best;
    }
    grid_sync(nb);

    // ---------------- greedy loop: GEMV entirely from SMEM ----------------
    float decay_t = 1.0f;
    for (int t = 0; t < KSEL; t++) {
        unsigned long long w = (tid < nb) ? __ldcg(&g_best[t & 1][tid]) : 0ull;
        w = blk_max_u64(w, sh_u64);
        if (tid == 0) sh_idx = (int)(~(unsigned int)(w & 0xFFFFFFFFull));
        __syncthreads();
        const int idx = sh_idx;

        if (bid == 0 && tid == 0) {
            g_err[t] = __ldcg(&g_rel[idx]) * decay_t;
            g_sel[t] = idx;
        }

        if (t < KSEL - 1) {
            // winner vector from global fp16 copy (L2), same element layout as rows
            const uint4* Vh = reinterpret_cast<const uint4*>(g_En) + (size_t)idx * 64;
            uint4 v0 = Vh[lid];
            uint4 v1 = Vh[32 + lid];
            __half2 vh[8];
            {
                const __half2* p0 = reinterpret_cast<const __half2*>(&v0);
                const __half2* p1 = reinterpret_cast<const __half2*>(&v1);
                #pragma unroll
                for (int q = 0; q < 4; q++) { vh[q] = p0[q]; vh[4 + q] = p1[q]; }
            }

            // 7-row smem GEMV
            const uint4* S4 = reinterpret_cast<const uint4*>(sm_rows);
            float f[RPW];
            #pragma unroll
            for (int i = 0; i < RPW; i++) {
                const int lr = wid * RPW + i;
                uint4 a0 = S4[lr * 64 + lid];
                uint4 a1 = S4[lr * 64 + 32 + lid];
                const __half2* h0 = reinterpret_cast<const __half2*>(&a0);
                const __half2* h1 = reinterpret_cast<const __half2*>(&a1);
                __half2 acc_a = __hmul2(h0[0], vh[0]);
                __half2 acc_b = __hmul2(h0[1], vh[1]);
                acc_a = __hfma2(h0[2], vh[2], acc_a);
                acc_b = __hfma2(h0[3], vh[3], acc_b);
                acc_a = __hfma2(h1[0], vh[4], acc_a);
                acc_b = __hfma2(h1[1], vh[5], acc_b);
                acc_a = __hfma2(h1[2], vh[6], acc_a);
                acc_b = __hfma2(h1[3], vh[7], acc_b);
                float2 fa = __half22float2(acc_a);
                float2 fb = __half22float2(acc_b);
                f[i] = (fa.x + fa.y) + (fb.x + fb.y);
            }
            #pragma unroll
            for (int o = 16; o > 0; o >>= 1) {
                #pragma unroll
                for (int i = 0; i < RPW; i++) f[i] += __shfl_xor_sync(0xffffffffu, f[i], o);
            }
            float mysim = 0.f;
            #pragma unroll
            for (int i = 0; i < RPW; i++) if (lid == i) mysim = f[i];

            unsigned long long best = 0ull;
            const float decay_next = decay_t * DECAYF;
            if (mine) {
                myms = (myrow == idx) ? 1e30f : fmaxf(myms, mysim);
                float score = decay_next * myrel - LAMBDA * myms;
                best = pack_si(score, myrow);
            }
            best = blk_max_u64(best, sh_u64);
            if (tid == 0) g_best[(t + 1) & 1][bid] = best;
            grid_sync(nb);
        }
        decay_t *= DECAYF;
    }

    // ---------------- final: err sum + mmr over selected 16x16 (block 0) ----------------
    if (bid == 0) {
        __syncthreads();
        for (int p = wid; p < KSEL * KSEL; p += 32) {
            int a = p >> 4, b = p & 15;
            int ia = g_sel[a], ib = g_sel[b];
            const uint4* Ea = reinterpret_cast<const uint4*>(g_En) + (size_t)ia * 64;
            const uint4* Eb = reinterpret_cast<const uint4*>(g_En) + (size_t)ib * 64;
            float acc = 0.f;
            #pragma unroll
            for (int j = 0; j < 2; j++) {
                uint4 x = Ea[j * 32 + lid];
                uint4 y = Eb[j * 32 + lid];
                const __half2* hx = reinterpret_cast<const __half2*>(&x);
                const __half2* hy = reinterpret_cast<const __half2*>(&y);
                #pragma unroll
                for (int q = 0; q < 4; q++) {
                    float2 fx = __half22float2(hx[q]);
                    float2 fy = __half22float2(hy[q]);
                    acc = fmaf(fx.x, fy.x, acc);
                    acc = fmaf(fx.y, fy.y, acc);
                }
            }
            acc = warp_sum_xor(acc);
            if (lid == 0) sh_sims[a][b] = acc;
        }
        __syncthreads();
        if (tid == 0) {
            float se = 0.f;
            #pragma unroll
            for (int t = 0; t < KSEL; t++) se += g_err[t];
            float sm = 0.f;
            #pragma unroll
            for (int a = 0; a < KSEL; a++) {
                float mx = -INFINITY;
                #pragma unroll
                for (int b = 0; b < KSEL; b++) mx = fmaxf(mx, sh_sims[a][b]);
                sm += mx;
            }
            out[0] = -se - LAMBDA * sm;
        }
    }
}

extern "C" void kernel_launch(void* const* d_in, const int* in_sizes, int n_in,
                              void* d_out, int out_size) {
    (void)in_sizes; (void)n_in; (void)out_size;
    const float* pred = (const float*)d_in[0];
    const float* E    = (const float*)d_in[5];   // explanation_embeddings [32768, 512]
    float* out        = (float*)d_out;

    int dev = 0;
    cudaGetDevice(&dev);
    int nsm = 0;
    cudaDeviceGetAttribute(&nsm, cudaDevAttrMultiProcessorCount, dev);
    if (nsm <= 0) nsm = 148;
    if (nsm > MAXB) nsm = MAXB;

    cudaFuncSetAttribute(ranking_kernel,
                         cudaFuncAttributeMaxDynamicSharedMemorySize, SMEM_DYN);
    ranking_kernel<<<nsm, NTHREADS, SMEM_DYN>>>(pred, E, out, nsm);
}